// round 5
// baseline (speedup 1.0000x reference)
#include <cuda_runtime.h>

#define N_NODES 100000
#define N_EDGES 1000000
#define D 64
#define CAP 128          // bucket capacity per destination (avg degree = 10)
#define OVF_CAP 8192     // overflow safety valve (never hit in practice)

// ---------------------------------------------------------------------------
// Scratch (__device__ globals: allocation-free rule)
// ---------------------------------------------------------------------------
__device__ float g_agg[(size_t)N_NODES * D];                 // 25.6 MB
__device__ unsigned long long g_buckets[(size_t)N_NODES * CAP];  // 102.4 MB
__device__ int g_cnt[N_NODES];
__device__ int g_ovf_cnt;
__device__ int g_ovf_src[OVF_CAP];
__device__ int g_ovf_dst[OVF_CAP];
__device__ float g_ovf_w[OVF_CAP];

// ---------------------------------------------------------------------------
// K0: zero the per-destination counters + overflow cursor
// ---------------------------------------------------------------------------
__global__ void zero_kernel() {
    int i = blockIdx.x * blockDim.x + threadIdx.x;
    if (i < N_NODES) g_cnt[i] = 0;
    if (i == 0) g_ovf_cnt = 0;
}

// ---------------------------------------------------------------------------
// K1: bucket fill — one thread per edge. Only int32 atomics (cheap on LTS).
// Packs (src, w) into one 8-byte word.
// ---------------------------------------------------------------------------
__global__ void fill_kernel(const int* __restrict__ edge_index,
                            const float* __restrict__ edge_weight) {
    int e = blockIdx.x * blockDim.x + threadIdx.x;
    if (e >= N_EDGES) return;
    int src = edge_index[e];
    int dst = edge_index[N_EDGES + e];
    float w = edge_weight[e];
    int pos = atomicAdd(&g_cnt[dst], 1);
    if (pos < CAP) {
        unsigned long long pair = (unsigned long long)(unsigned)src |
                                  ((unsigned long long)__float_as_uint(w) << 32);
        g_buckets[(size_t)dst * CAP + pos] = pair;
    } else {
        int o = atomicAdd(&g_ovf_cnt, 1);
        if (o < OVF_CAP) {
            g_ovf_src[o] = src;
            g_ovf_dst[o] = dst;
            g_ovf_w[o] = w;
        }
    }
}

// ---------------------------------------------------------------------------
// K2: warp-per-destination accumulate. lane l owns floats [2l, 2l+1].
// acc initialized to features[dst] (fuses the residual; no init kernel).
// 1-deep prefetch of the next (src,w) pair overlaps the gather latency.
// No floating-point atomics anywhere.
// ---------------------------------------------------------------------------
__global__ void __launch_bounds__(256)
accum_kernel(const float* __restrict__ feat) {
    int gwarp = (blockIdx.x * blockDim.x + threadIdx.x) >> 5;
    int lane = threadIdx.x & 31;
    if (gwarp >= N_NODES) return;
    const int dst = gwarp;

    const float2* __restrict__ f2 = (const float2*)feat;
    float2 acc = f2[(size_t)dst * 32 + lane];  // residual

    int c = g_cnt[dst];
    if (c > CAP) c = CAP;

    const unsigned long long* __restrict__ bk = g_buckets + (size_t)dst * CAP;
    unsigned long long pair = (c > 0) ? bk[0] : 0ULL;

    for (int i = 0; i < c; i++) {
        unsigned long long nxt = (i + 1 < c) ? bk[i + 1] : 0ULL;
        int s = (int)(unsigned)pair;
        float w = __uint_as_float((unsigned)(pair >> 32));
        float2 v = f2[(size_t)s * 32 + lane];
        acc.x = fmaf(w, v.x, acc.x);
        acc.y = fmaf(w, v.y, acc.y);
        pair = nxt;
    }
    ((float2*)g_agg)[(size_t)dst * 32 + lane] = acc;
}

// ---------------------------------------------------------------------------
// K3: overflow cleanup (runs after K2; empty in practice)
// ---------------------------------------------------------------------------
__global__ void overflow_kernel(const float* __restrict__ feat) {
    int i = blockIdx.x * blockDim.x + threadIdx.x;
    int n = g_ovf_cnt;
    if (n > OVF_CAP) n = OVF_CAP;
    if (i >= n) return;
    int s = g_ovf_src[i], d = g_ovf_dst[i];
    float w = g_ovf_w[i];
    for (int k = 0; k < D; k++)
        atomicAdd(&g_agg[(size_t)d * D + k], w * feat[(size_t)s * D + k]);
}

// ---------------------------------------------------------------------------
// K4: out = agg @ W^T + b with packed fma.rn.f32x2 (2 FMAs/instr).
// thread x = output column, y = row slot. Even/odd k split into the two
// packed halves; recombined at the end.
// ---------------------------------------------------------------------------
__global__ void __launch_bounds__(256)
gemm_kernel(const float* __restrict__ W,
            const float* __restrict__ b,
            float* __restrict__ out) {
    __shared__ float arow[4][D];

    const int tx = threadIdx.x;  // 0..63
    const int ty = threadIdx.y;  // 0..3

    // W row tx packed as 32 x (2 floats)
    unsigned long long wreg[D / 2];
    const unsigned long long* Wp = (const unsigned long long*)(W + (size_t)tx * D);
#pragma unroll
    for (int j = 0; j < D / 2; j++) wreg[j] = Wp[j];
    const float bias = b[tx];

    for (int row = blockIdx.x * 4 + ty; row < N_NODES; row += gridDim.x * 4) {
        arow[ty][tx] = g_agg[(size_t)row * D + tx];
        __syncthreads();

        unsigned long long acc2 = 0ULL;  // {0.f, 0.f}
        const unsigned long long* ap = (const unsigned long long*)arow[ty];
#pragma unroll
        for (int j = 0; j < D / 2; j++) {
            asm("fma.rn.f32x2 %0, %1, %2, %3;"
                : "=l"(acc2)
                : "l"(ap[j]), "l"(wreg[j]), "l"(acc2));
        }
        float lo = __uint_as_float((unsigned)acc2);
        float hi = __uint_as_float((unsigned)(acc2 >> 32));
        out[(size_t)row * D + tx] = lo + hi + bias;
        __syncthreads();
    }
}

// ---------------------------------------------------------------------------
extern "C" void kernel_launch(void* const* d_in, const int* in_sizes, int n_in,
                              void* d_out, int out_size) {
    const float* features = (const float*)d_in[0];
    const int* edge_index = (const int*)d_in[1];
    const float* edge_weight = (const float*)d_in[2];
    const float* W = (const float*)d_in[3];
    const float* b = (const float*)d_in[4];
    float* out = (float*)d_out;

    zero_kernel<<<(N_NODES + 255) / 256, 256>>>();
    fill_kernel<<<(N_EDGES + 255) / 256, 256>>>(edge_index, edge_weight);
    accum_kernel<<<(N_NODES * 32 + 255) / 256, 256>>>(features);
    overflow_kernel<<<OVF_CAP / 256, 256>>>(features);
    dim3 gblock(64, 4);
    gemm_kernel<<<1480, gblock>>>(W, b, out);
}

// round 6
// speedup vs baseline: 1.0170x; 1.0170x over previous
#include <cuda_runtime.h>

#define N_NODES 100000
#define N_EDGES 1000000
#define D 64
#define CAP 32           // bucket row = 256B = one warp LDG; P(deg>=32)~6e-9
#define OVF_CAP 8192     // overflow safety valve

// ---------------------------------------------------------------------------
// Scratch (__device__ globals: allocation-free rule)
// ---------------------------------------------------------------------------
__device__ float g_agg[(size_t)N_NODES * D];                     // 25.6 MB
__device__ unsigned long long g_buckets[(size_t)N_NODES * CAP];  // 25.6 MB
__device__ int g_cnt[N_NODES];
__device__ int g_ovf_cnt;
__device__ int g_ovf_src[OVF_CAP];
__device__ int g_ovf_dst[OVF_CAP];
__device__ float g_ovf_w[OVF_CAP];

// ---------------------------------------------------------------------------
// K0: zero per-destination counters + overflow cursor
// ---------------------------------------------------------------------------
__global__ void zero_kernel() {
    int i = blockIdx.x * blockDim.x + threadIdx.x;
    if (i < N_NODES) g_cnt[i] = 0;
    if (i == 0) g_ovf_cnt = 0;
}

// ---------------------------------------------------------------------------
// K1: bucket fill — one thread per edge, int32 atomics only.
// Buckets are L2-resident (25.6 MB), so the scattered 8B stores stay in L2.
// ---------------------------------------------------------------------------
__global__ void fill_kernel(const int* __restrict__ edge_index,
                            const float* __restrict__ edge_weight) {
    int e = blockIdx.x * blockDim.x + threadIdx.x;
    if (e >= N_EDGES) return;
    int src = edge_index[e];
    int dst = edge_index[N_EDGES + e];
    float w = edge_weight[e];
    int pos = atomicAdd(&g_cnt[dst], 1);
    if (pos < CAP) {
        unsigned long long pair = (unsigned long long)(unsigned)src |
                                  ((unsigned long long)__float_as_uint(w) << 32);
        g_buckets[(size_t)dst * CAP + pos] = pair;
    } else {
        int o = atomicAdd(&g_ovf_cnt, 1);
        if (o < OVF_CAP) {
            g_ovf_src[o] = src;
            g_ovf_dst[o] = dst;
            g_ovf_w[o] = w;
        }
    }
}

// ---------------------------------------------------------------------------
// K2: warp-per-destination accumulate. One coalesced LDG.64 pulls the whole
// 256B bucket row (lane i = pair i); pairs broadcast via shfl, so all gather
// addresses are register-resident early. 2-way unroll -> 2 independent
// gathers in flight per iteration. Residual fused into acc init.
// Zero floating-point atomics.
// ---------------------------------------------------------------------------
__global__ void __launch_bounds__(256)
accum_kernel(const float* __restrict__ feat) {
    int gwarp = (blockIdx.x * blockDim.x + threadIdx.x) >> 5;
    int lane = threadIdx.x & 31;
    if (gwarp >= N_NODES) return;
    const int dst = gwarp;

    const float2* __restrict__ f2 = (const float2*)feat;
    float2 acc = f2[(size_t)dst * 32 + lane];  // residual

    int c = g_cnt[dst];
    if (c > CAP) c = CAP;

    // whole bucket row in one coalesced load: lane i holds pair i
    unsigned long long mypair = g_buckets[(size_t)dst * CAP + lane];

    int i = 0;
    for (; i + 2 <= c; i += 2) {
        unsigned long long p0 = __shfl_sync(0xffffffffu, mypair, i);
        unsigned long long p1 = __shfl_sync(0xffffffffu, mypair, i + 1);
        int s0 = (int)(unsigned)p0;
        int s1 = (int)(unsigned)p1;
        float w0 = __uint_as_float((unsigned)(p0 >> 32));
        float w1 = __uint_as_float((unsigned)(p1 >> 32));
        float2 v0 = f2[(size_t)s0 * 32 + lane];
        float2 v1 = f2[(size_t)s1 * 32 + lane];
        acc.x = fmaf(w0, v0.x, acc.x);
        acc.y = fmaf(w0, v0.y, acc.y);
        acc.x = fmaf(w1, v1.x, acc.x);
        acc.y = fmaf(w1, v1.y, acc.y);
    }
    if (i < c) {
        unsigned long long p0 = __shfl_sync(0xffffffffu, mypair, i);
        int s0 = (int)(unsigned)p0;
        float w0 = __uint_as_float((unsigned)(p0 >> 32));
        float2 v0 = f2[(size_t)s0 * 32 + lane];
        acc.x = fmaf(w0, v0.x, acc.x);
        acc.y = fmaf(w0, v0.y, acc.y);
    }
    ((float2*)g_agg)[(size_t)dst * 32 + lane] = acc;
}

// ---------------------------------------------------------------------------
// K3: overflow cleanup (statistically never runs; single small block)
// ---------------------------------------------------------------------------
__global__ void overflow_kernel(const float* __restrict__ feat) {
    int n = g_ovf_cnt;
    if (n > OVF_CAP) n = OVF_CAP;
    for (int i = threadIdx.x; i < n; i += blockDim.x) {
        int s = g_ovf_src[i], d = g_ovf_dst[i];
        float w = g_ovf_w[i];
        for (int k = 0; k < D; k++)
            atomicAdd(&g_agg[(size_t)d * D + k], w * feat[(size_t)s * D + k]);
    }
}

// ---------------------------------------------------------------------------
// K4: out = agg @ W^T + b with packed fma.rn.f32x2 (2 FMAs/instr).
// ---------------------------------------------------------------------------
__global__ void __launch_bounds__(256)
gemm_kernel(const float* __restrict__ W,
            const float* __restrict__ b,
            float* __restrict__ out) {
    __shared__ float arow[4][D];

    const int tx = threadIdx.x;  // 0..63 output column
    const int ty = threadIdx.y;  // 0..3 row slot

    unsigned long long wreg[D / 2];
    const unsigned long long* Wp = (const unsigned long long*)(W + (size_t)tx * D);
#pragma unroll
    for (int j = 0; j < D / 2; j++) wreg[j] = Wp[j];
    const float bias = b[tx];

    for (int row = blockIdx.x * 4 + ty; row < N_NODES; row += gridDim.x * 4) {
        arow[ty][tx] = g_agg[(size_t)row * D + tx];
        __syncthreads();

        unsigned long long acc2 = 0ULL;
        const unsigned long long* ap = (const unsigned long long*)arow[ty];
#pragma unroll
        for (int j = 0; j < D / 2; j++) {
            asm("fma.rn.f32x2 %0, %1, %2, %3;"
                : "=l"(acc2)
                : "l"(ap[j]), "l"(wreg[j]), "l"(acc2));
        }
        float lo = __uint_as_float((unsigned)acc2);
        float hi = __uint_as_float((unsigned)(acc2 >> 32));
        out[(size_t)row * D + tx] = lo + hi + bias;
        __syncthreads();
    }
}

// ---------------------------------------------------------------------------
extern "C" void kernel_launch(void* const* d_in, const int* in_sizes, int n_in,
                              void* d_out, int out_size) {
    const float* features = (const float*)d_in[0];
    const int* edge_index = (const int*)d_in[1];
    const float* edge_weight = (const float*)d_in[2];
    const float* W = (const float*)d_in[3];
    const float* b = (const float*)d_in[4];
    float* out = (float*)d_out;

    zero_kernel<<<(N_NODES + 255) / 256, 256>>>();
    fill_kernel<<<(N_EDGES + 255) / 256, 256>>>(edge_index, edge_weight);
    accum_kernel<<<(N_NODES * 32 + 255) / 256, 256>>>(features);
    overflow_kernel<<<1, 256>>>(features);
    dim3 gblock(64, 4);
    gemm_kernel<<<1480, gblock>>>(W, b, out);
}